// round 1
// baseline (speedup 1.0000x reference)
#include <cuda_runtime.h>
#include <cstdint>

#define D    1024
#define E    8
#define FF   4096
#define CAP  2048
#define T    8192
#define W_IMP    0.01f
#define W_LOAD   0.01f
#define LAMBDA_Z 0.001f
#define W_PEN    0.01f

typedef unsigned long long ull;

// ---------------- device scratch (allocation-free: __device__ globals) -------
__device__ int   g_e1[T], g_e2[T];
__device__ float g_g1n[T], g_g2n[T];
__device__ float g_ws[2][T];          // combine weight per slot per token (0 if masked)
__device__ int   g_row[2][T];         // e*CAP+pos if surviving else -1
__device__ int   g_idx[2][E * CAP];   // token index per buffer row, -1 = hole
__device__ int   g_cnt[2][E];         // live rows per (slot, expert)
__device__ float g_part[(T / 8) * 26];
__device__ float g_red[26];
__device__ float g_imp[E];
__device__ float g_H[(size_t)2 * E * CAP * FF];  // 512 MB hidden scratch
__device__ float g_Y[(size_t)2 * E * CAP * D];   // 128 MB output scratch

// ---------------- f32x2 helpers ---------------------------------------------
__device__ __forceinline__ ull pack2(float v) {
    ull r; asm("mov.b64 %0, {%1,%1};" : "=l"(r) : "f"(v)); return r;
}
__device__ __forceinline__ void fma2(ull& d, ull a, ull b) {
    asm("fma.rn.f32x2 %0, %1, %2, %3;" : "=l"(d) : "l"(a), "l"(b), "l"(d));
}
__device__ __forceinline__ float2 unpack2(ull v) {
    float2 f; asm("mov.b64 {%0,%1}, %2;" : "=f"(f.x), "=f"(f.y) : "l"(v)); return f;
}
__device__ __forceinline__ float gelu_tanh(float v) {
    const float c = 0.7978845608028654f;
    float u = c * (v + 0.044715f * v * v * v);
    return 0.5f * v * (1.0f + tanhf(u));
}

// ---------------- gating: logits, softmaxes, top-2, loss partials ------------
__global__ void gate_kernel(const float* __restrict__ x, const float* __restrict__ gw) {
    __shared__ float sgw[E * D];
    __shared__ float wpart[8][26];
    int tid = threadIdx.x;
    for (int i = tid; i < E * D; i += 256) sgw[i] = gw[i];
    __syncthreads();

    int warp = tid >> 5, lane = tid & 31;
    int t = blockIdx.x * 8 + warp;

    float acc[E];
#pragma unroll
    for (int e = 0; e < E; e++) acc[e] = 0.f;
    const float* xr = x + (size_t)t * D;
#pragma unroll 4
    for (int j = 0; j < D / 32; j++) {
        float xv = xr[j * 32 + lane];
#pragma unroll
        for (int e = 0; e < E; e++) acc[e] += xv * sgw[e * D + j * 32 + lane];
    }
#pragma unroll
    for (int e = 0; e < E; e++)
#pragma unroll
        for (int off = 16; off; off >>= 1)
            acc[e] += __shfl_xor_sync(0xffffffffu, acc[e], off);

    // all lanes now hold the 8 logits; lane 0 writes
    float m = acc[0];
#pragma unroll
    for (int e = 1; e < E; e++) m = fmaxf(m, acc[e]);

    float p166[E]; float s166 = 0.f;
#pragma unroll
    for (int e = 0; e < E; e++) { p166[e] = expf((acc[e] - m) / 1.66f); s166 += p166[e]; }
    float pa = 0.f;
#pragma unroll
    for (int e = 0; e < E; e++) { p166[e] /= s166; pa += p166[e] * (1.f - p166[e]); }

    float p[E]; float s = 0.f;
#pragma unroll
    for (int e = 0; e < E; e++) { p[e] = expf(acc[e] - m); s += p[e]; }
    float lse = m + logf(s);
#pragma unroll
    for (int e = 0; e < E; e++) p[e] /= s;

    int e1 = 0; float p1 = p[0];
#pragma unroll
    for (int e = 1; e < E; e++) if (p[e] > p1) { p1 = p[e]; e1 = e; }
    int e2 = -1; float p2 = -1.f;
#pragma unroll
    for (int e = 0; e < E; e++) if (e != e1 && p[e] > p2) { p2 = p[e]; e2 = e; }

    float den = p1 + p2;
    if (lane == 0) {
        g_e1[t] = e1; g_e2[t] = e2;
        g_g1n[t] = p1 / den; g_g2n[t] = p2 / den;
        wpart[warp][0] = pa;
#pragma unroll
        for (int e = 0; e < E; e++) wpart[warp][1 + e] = p166[e];
        wpart[warp][9] = lse * lse;
#pragma unroll
        for (int e = 0; e < E; e++) wpart[warp][10 + e] = p[e];
#pragma unroll
        for (int e = 0; e < E; e++) wpart[warp][18 + e] = (e == e1) ? 1.f : 0.f;
    }
    __syncthreads();
    if (tid < 26) {
        float sum = 0.f;
        for (int w = 0; w < 8; w++) sum += wpart[w][tid];
        g_part[blockIdx.x * 26 + tid] = sum;
    }
}

// deterministic fixed-order reduction of per-block partials
__global__ void reduce_kernel() {
    int j = threadIdx.x;
    if (j < 26) {
        float s = 0.f;
        for (int b = 0; b < T / 8; b++) s += g_part[b * 26 + j];
        g_red[j] = s;
    }
}

// ---------------- per-expert prefix-sum positions, masks, index tables -------
__global__ void scan_kernel(const float* __restrict__ rnd) {
    __shared__ int s[E][1024];
    int tid = threadIdx.x;
    for (int i = tid; i < 2 * E * CAP; i += 1024) ((int*)g_idx)[i] = -1;

    int t0 = tid * 8;

    // ---- slot 1 ----
    int ev[8];
#pragma unroll
    for (int j = 0; j < 8; j++) ev[j] = g_e1[t0 + j];
    int c[E];
#pragma unroll
    for (int e = 0; e < E; e++) c[e] = 0;
#pragma unroll
    for (int j = 0; j < 8; j++) c[ev[j]]++;
#pragma unroll
    for (int e = 0; e < E; e++) s[e][tid] = c[e];
    __syncthreads();
    for (int off = 1; off < 1024; off <<= 1) {
        int r[E];
#pragma unroll
        for (int e = 0; e < E; e++) r[e] = (tid >= off) ? s[e][tid - off] : 0;
        __syncthreads();
#pragma unroll
        for (int e = 0; e < E; e++) s[e][tid] += r[e];
        __syncthreads();
    }
    int excl[E], tot[E];
#pragma unroll
    for (int e = 0; e < E; e++) { excl[e] = s[e][tid] - c[e]; tot[e] = s[e][1023]; }

    float impL[E];
#pragma unroll
    for (int e = 0; e < E; e++) impL[e] = 0.f;

#pragma unroll
    for (int j = 0; j < 8; j++) {
        int t = t0 + j, e = ev[j];
        int p = excl[e]++;
        bool mk = p < CAP;
        float w = mk ? g_g1n[t] : 0.f;
        g_ws[0][t] = w;
        if (mk) { g_idx[0][e * CAP + p] = t; g_row[0][t] = e * CAP + p; }
        else    { g_row[0][t] = -1; }
        impL[e] += w;
    }
    if (tid == 0)
        for (int e = 0; e < E; e++) g_cnt[0][e] = tot[e] < CAP ? tot[e] : CAP;
    __syncthreads();

    // ---- slot 2 ----
#pragma unroll
    for (int j = 0; j < 8; j++) ev[j] = g_e2[t0 + j];
#pragma unroll
    for (int e = 0; e < E; e++) c[e] = 0;
#pragma unroll
    for (int j = 0; j < 8; j++) c[ev[j]]++;
#pragma unroll
    for (int e = 0; e < E; e++) s[e][tid] = c[e];
    __syncthreads();
    for (int off = 1; off < 1024; off <<= 1) {
        int r[E];
#pragma unroll
        for (int e = 0; e < E; e++) r[e] = (tid >= off) ? s[e][tid - off] : 0;
        __syncthreads();
#pragma unroll
        for (int e = 0; e < E; e++) s[e][tid] += r[e];
        __syncthreads();
    }
#pragma unroll
    for (int e = 0; e < E; e++) { excl[e] = s[e][tid] - c[e]; tot[e] = s[e][1023]; }

#pragma unroll
    for (int j = 0; j < 8; j++) {
        int t = t0 + j, e = ev[j];
        int p = excl[e]++;
        float g2n = g_g2n[t];
        bool mk = (p < CAP) && (rnd[t] < 2.f * g2n);
        float w = mk ? g2n : 0.f;
        g_ws[1][t] = w;
        if (mk) { g_idx[1][e * CAP + p] = t; g_row[1][t] = e * CAP + p; }
        else    { g_row[1][t] = -1; }
        impL[e] += w;
    }
    if (tid == 0)
        for (int e = 0; e < E; e++) g_cnt[1][e] = tot[e] < CAP ? tot[e] : CAP;
    __syncthreads();

    // ---- deterministic imp reduction (reuse smem as float) ----
    float* f = (float*)s;
#pragma unroll
    for (int e = 0; e < E; e++) f[e * 1024 + tid] = impL[e];
    __syncthreads();
    for (int off = 512; off; off >>= 1) {
        if (tid < off)
#pragma unroll
            for (int e = 0; e < E; e++) f[e * 1024 + tid] += f[e * 1024 + tid + off];
        __syncthreads();
    }
    if (tid < E) g_imp[tid] = f[tid * 1024];
}

// ---------------- aux scalar -------------------------------------------------
__global__ void aux_kernel(float* __restrict__ out) {
    if (threadIdx.x == 0) {
        const float Tf = (float)T;
        float penalty_a = g_red[0] / (Tf * (float)E);
        float pb_acc = 0.f;
        for (int e = 0; e < E; e++) { float pm = g_red[1 + e] / Tf; pb_acc += pm * (1.f - pm); }
        float penalty_b = 1.f / (float)E - pb_acc / (float)E;
        float penalty = W_PEN * (penalty_a + penalty_b);
        float z = LAMBDA_Z * g_red[9] / Tf;
        float load = 0.f;
        for (int e = 0; e < E; e++) load += (g_red[18 + e] / Tf) * (g_red[10 + e] / Tf);
        load *= W_LOAD * (float)E;
        float mean = 0.f;
        for (int e = 0; e < E; e++) mean += g_imp[e];
        mean /= (float)E;
        float var = 0.f;
        for (int e = 0; e < E; e++) { float d = g_imp[e] - mean; var += d * d; }
        var /= (float)E;
        float imp_loss = W_IMP * var / (mean * mean);
        out[(size_t)T * D] = penalty + z + load + imp_loss;
    }
}

// ---------------- FFN GEMM 1: H = gelu(gather(X) @ w1 + b1) ------------------
__global__ __launch_bounds__(256) void ffn1_kernel(const float* __restrict__ x,
                                                   const float* __restrict__ w1,
                                                   const float* __restrict__ b1) {
    int g = blockIdx.z, slot = g >> 3, e = g & 7;
    int cnt = g_cnt[slot][e];
    int m0 = blockIdx.y * 128;
    if (m0 >= cnt) return;
    int n0 = blockIdx.x * 128;

    __shared__ float As[2][8][128];
    __shared__ float Bs[2][8][128];
    __shared__ int rows[128];
    int tid = threadIdx.x;
    if (tid < 128) rows[tid] = g_idx[slot][e * CAP + m0 + tid];
    __syncthreads();

    int am = tid & 127, ak = (tid >> 7) << 2;
    int bk = tid >> 5,  bn = (tid & 31) << 2;
    const float* Ap = (rows[am] >= 0) ? (x + (size_t)rows[am] * D + ak) : nullptr;
    const float* Bp = w1 + (size_t)e * D * FF + (size_t)bk * FF + n0 + bn;

    float4 af = Ap ? *(const float4*)Ap : make_float4(0.f, 0.f, 0.f, 0.f);
    float4 bf = *(const float4*)Bp;
    As[0][ak + 0][am] = af.x; As[0][ak + 1][am] = af.y;
    As[0][ak + 2][am] = af.z; As[0][ak + 3][am] = af.w;
    *(float4*)&Bs[0][bk][bn] = bf;
    __syncthreads();

    int tx = tid & 15, ty = tid >> 4;
    ull acc[8][4];
#pragma unroll
    for (int i = 0; i < 8; i++)
#pragma unroll
        for (int j = 0; j < 4; j++) acc[i][j] = 0ull;

    int buf = 0;
    for (int kb = 0; kb < D; kb += 8) {
        float4 af2, bf2;
        bool more = (kb + 8) < D;
        if (more) {
            af2 = Ap ? *(const float4*)(Ap + kb + 8) : make_float4(0.f, 0.f, 0.f, 0.f);
            bf2 = *(const float4*)(Bp + (size_t)(kb + 8) * FF);
        }
#pragma unroll
        for (int kk = 0; kk < 8; kk++) {
            const ull* b2 = (const ull*)&Bs[buf][kk][tx * 8];
            ull bq0 = b2[0], bq1 = b2[1], bq2 = b2[2], bq3 = b2[3];
#pragma unroll
            for (int i = 0; i < 8; i++) {
                ull ap = pack2(As[buf][kk][ty * 8 + i]);
                fma2(acc[i][0], ap, bq0);
                fma2(acc[i][1], ap, bq1);
                fma2(acc[i][2], ap, bq2);
                fma2(acc[i][3], ap, bq3);
            }
        }
        if (more) {
            int nb = buf ^ 1;
            As[nb][ak + 0][am] = af2.x; As[nb][ak + 1][am] = af2.y;
            As[nb][ak + 2][am] = af2.z; As[nb][ak + 3][am] = af2.w;
            *(float4*)&Bs[nb][bk][bn] = bf2;
            __syncthreads();
            buf = nb;
        }
    }

    const float* be = b1 + e * FF + n0 + tx * 8;
#pragma unroll
    for (int i = 0; i < 8; i++) {
        int m = m0 + ty * 8 + i;
        float2 u0 = unpack2(acc[i][0]), u1 = unpack2(acc[i][1]);
        float2 u2 = unpack2(acc[i][2]), u3 = unpack2(acc[i][3]);
        float o[8] = { u0.x, u0.y, u1.x, u1.y, u2.x, u2.y, u3.x, u3.y };
#pragma unroll
        for (int n = 0; n < 8; n++) o[n] = gelu_tanh(o[n] + be[n]);
        size_t base = ((size_t)g * CAP + m) * FF + n0 + tx * 8;
        *(float4*)&g_H[base]     = make_float4(o[0], o[1], o[2], o[3]);
        *(float4*)&g_H[base + 4] = make_float4(o[4], o[5], o[6], o[7]);
    }
}

// ---------------- FFN GEMM 2: Y = H @ w2 + b2 --------------------------------
__global__ __launch_bounds__(256) void ffn2_kernel(const float* __restrict__ w2,
                                                   const float* __restrict__ b2) {
    int g = blockIdx.z, slot = g >> 3, e = g & 7;
    int cnt = g_cnt[slot][e];
    int m0 = blockIdx.y * 128;
    if (m0 >= cnt) return;
    int n0 = blockIdx.x * 128;

    __shared__ float As[2][8][128];
    __shared__ float Bs[2][8][128];
    int tid = threadIdx.x;

    int am = tid & 127, ak = (tid >> 7) << 2;
    int bk = tid >> 5,  bn = (tid & 31) << 2;
    const float* Ap = g_H + ((size_t)g * CAP + m0 + am) * FF + ak;
    const float* Bp = w2 + (size_t)e * FF * D + (size_t)bk * D + n0 + bn;

    float4 af = *(const float4*)Ap;
    float4 bf = *(const float4*)Bp;
    As[0][ak + 0][am] = af.x; As[0][ak + 1][am] = af.y;
    As[0][ak + 2][am] = af.z; As[0][ak + 3][am] = af.w;
    *(float4*)&Bs[0][bk][bn] = bf;
    __syncthreads();

    int tx = tid & 15, ty = tid >> 4;
    ull acc[8][4];
#pragma unroll
    for (int i = 0; i < 8; i++)
#pragma unroll
        for (int j = 0; j < 4; j++) acc[i][j] = 0ull;

    int buf = 0;
    for (int kb = 0; kb < FF; kb += 8) {
        float4 af2, bf2;
        bool more = (kb + 8) < FF;
        if (more) {
            af2 = *(const float4*)(Ap + kb + 8);
            bf2 = *(const float4*)(Bp + (size_t)(kb + 8) * D);
        }
#pragma unroll
        for (int kk = 0; kk < 8; kk++) {
            const ull* b2v = (const ull*)&Bs[buf][kk][tx * 8];
            ull bq0 = b2v[0], bq1 = b2v[1], bq2 = b2v[2], bq3 = b2v[3];
#pragma unroll
            for (int i = 0; i < 8; i++) {
                ull ap = pack2(As[buf][kk][ty * 8 + i]);
                fma2(acc[i][0], ap, bq0);
                fma2(acc[i][1], ap, bq1);
                fma2(acc[i][2], ap, bq2);
                fma2(acc[i][3], ap, bq3);
            }
        }
        if (more) {
            int nb = buf ^ 1;
            As[nb][ak + 0][am] = af2.x; As[nb][ak + 1][am] = af2.y;
            As[nb][ak + 2][am] = af2.z; As[nb][ak + 3][am] = af2.w;
            *(float4*)&Bs[nb][bk][bn] = bf2;
            __syncthreads();
            buf = nb;
        }
    }

    const float* be = b2 + e * D + n0 + tx * 8;
#pragma unroll
    for (int i = 0; i < 8; i++) {
        int m = m0 + ty * 8 + i;
        float2 u0 = unpack2(acc[i][0]), u1 = unpack2(acc[i][1]);
        float2 u2 = unpack2(acc[i][2]), u3 = unpack2(acc[i][3]);
        float o[8] = { u0.x, u0.y, u1.x, u1.y, u2.x, u2.y, u3.x, u3.y };
#pragma unroll
        for (int n = 0; n < 8; n++) o[n] += be[n];
        size_t base = ((size_t)g * CAP + m) * D + n0 + tx * 8;
        *(float4*)&g_Y[base]     = make_float4(o[0], o[1], o[2], o[3]);
        *(float4*)&g_Y[base + 4] = make_float4(o[4], o[5], o[6], o[7]);
    }
}

// ---------------- combine: y[t] = w1*Y1[row1] + w2*Y2[row2] ------------------
__global__ void combine_kernel(float* __restrict__ out) {
    int t = blockIdx.x;
    int d = threadIdx.x * 4;
    int r1 = g_row[0][t], r2 = g_row[1][t];
    float w1 = g_ws[0][t], w2 = g_ws[1][t];
    float4 v = make_float4(0.f, 0.f, 0.f, 0.f);
    if (r1 >= 0) {
        float4 a = *(const float4*)&g_Y[(size_t)r1 * D + d];
        v.x = w1 * a.x; v.y = w1 * a.y; v.z = w1 * a.z; v.w = w1 * a.w;
    }
    if (r2 >= 0) {
        float4 a = *(const float4*)&g_Y[((size_t)E * CAP + r2) * D + d];
        v.x += w2 * a.x; v.y += w2 * a.y; v.z += w2 * a.z; v.w += w2 * a.w;
    }
    *(float4*)&out[(size_t)t * D + d] = v;
}

// ---------------- launcher ---------------------------------------------------
extern "C" void kernel_launch(void* const* d_in, const int* in_sizes, int n_in,
                              void* d_out, int out_size) {
    const float* x   = (const float*)d_in[0];
    const float* gw  = (const float*)d_in[1];
    const float* w1  = (const float*)d_in[2];
    const float* b1  = (const float*)d_in[3];
    const float* w2  = (const float*)d_in[4];
    const float* b2  = (const float*)d_in[5];
    const float* rnd = (const float*)d_in[6];
    float* out = (float*)d_out;

    gate_kernel<<<T / 8, 256>>>(x, gw);
    reduce_kernel<<<1, 32>>>();
    scan_kernel<<<1, 1024>>>(rnd);
    aux_kernel<<<1, 32>>>(out);
    ffn1_kernel<<<dim3(FF / 128, CAP / 128, 2 * E), 256>>>(x, w1, b1);
    ffn2_kernel<<<dim3(D / 128, CAP / 128, 2 * E), 256>>>(w2, b2);
    combine_kernel<<<T, 256>>>(out);
}

// round 2
// speedup vs baseline: 1.0003x; 1.0003x over previous
#include <cuda_runtime.h>
#include <cstdint>

#define D    1024
#define E    8
#define FF   4096
#define CAP  2048
#define T    8192
#define W_IMP    0.01f
#define W_LOAD   0.01f
#define LAMBDA_Z 0.001f
#define W_PEN    0.01f

typedef unsigned long long ull;

// ---------------- device scratch (allocation-free: __device__ globals) -------
__device__ int   g_e1[T], g_e2[T];
__device__ float g_g1n[T], g_g2n[T];
__device__ float g_ws[2][T];          // combine weight per slot per token (0 if masked)
__device__ int   g_row[2][T];         // e*CAP+pos if surviving else -1
__device__ int   g_idx[2][E * CAP];   // token index per buffer row, -1 = hole
__device__ int   g_cnt[2][E];         // live rows per (slot, expert)
__device__ float g_part[(T / 8) * 26];
__device__ float g_red[26];
__device__ float g_imp[E];
__device__ float g_H[(size_t)2 * E * CAP * FF];  // 512 MB hidden scratch
__device__ float g_Y[(size_t)2 * E * CAP * D];   // 128 MB output scratch

// ---------------- f32x2 helpers ---------------------------------------------
__device__ __forceinline__ ull pack2(float v) {
    ull r; asm("mov.b64 %0, {%1,%1};" : "=l"(r) : "f"(v)); return r;
}
__device__ __forceinline__ void fma2(ull& d, ull a, ull b) {
    asm("fma.rn.f32x2 %0, %1, %2, %3;" : "=l"(d) : "l"(a), "l"(b), "l"(d));
}
__device__ __forceinline__ float2 unpack2(ull v) {
    float2 f; asm("mov.b64 {%0,%1}, %2;" : "=f"(f.x), "=f"(f.y) : "l"(v)); return f;
}
__device__ __forceinline__ float gelu_tanh(float v) {
    const float c = 0.7978845608028654f;
    float u = c * (v + 0.044715f * v * v * v);
    return 0.5f * v * (1.0f + tanhf(u));
}

// ---------------- gating: logits, softmaxes, top-2, loss partials ------------
__global__ void gate_kernel(const float* __restrict__ x, const float* __restrict__ gw) {
    __shared__ float sgw[E * D];
    __shared__ float wpart[8][26];
    int tid = threadIdx.x;
    for (int i = tid; i < E * D; i += 256) sgw[i] = gw[i];
    __syncthreads();

    int warp = tid >> 5, lane = tid & 31;
    int t = blockIdx.x * 8 + warp;

    float acc[E];
#pragma unroll
    for (int e = 0; e < E; e++) acc[e] = 0.f;
    const float* xr = x + (size_t)t * D;
#pragma unroll 4
    for (int j = 0; j < D / 32; j++) {
        float xv = xr[j * 32 + lane];
#pragma unroll
        for (int e = 0; e < E; e++) acc[e] += xv * sgw[e * D + j * 32 + lane];
    }
#pragma unroll
    for (int e = 0; e < E; e++)
#pragma unroll
        for (int off = 16; off; off >>= 1)
            acc[e] += __shfl_xor_sync(0xffffffffu, acc[e], off);

    // all lanes now hold the 8 logits; lane 0 writes
    float m = acc[0];
#pragma unroll
    for (int e = 1; e < E; e++) m = fmaxf(m, acc[e]);

    float p166[E]; float s166 = 0.f;
#pragma unroll
    for (int e = 0; e < E; e++) { p166[e] = expf((acc[e] - m) / 1.66f); s166 += p166[e]; }
    float pa = 0.f;
#pragma unroll
    for (int e = 0; e < E; e++) { p166[e] /= s166; pa += p166[e] * (1.f - p166[e]); }

    float p[E]; float s = 0.f;
#pragma unroll
    for (int e = 0; e < E; e++) { p[e] = expf(acc[e] - m); s += p[e]; }
    float lse = m + logf(s);
#pragma unroll
    for (int e = 0; e < E; e++) p[e] /= s;

    int e1 = 0; float p1 = p[0];
#pragma unroll
    for (int e = 1; e < E; e++) if (p[e] > p1) { p1 = p[e]; e1 = e; }
    int e2 = -1; float p2 = -1.f;
#pragma unroll
    for (int e = 0; e < E; e++) if (e != e1 && p[e] > p2) { p2 = p[e]; e2 = e; }

    float den = p1 + p2;
    if (lane == 0) {
        g_e1[t] = e1; g_e2[t] = e2;
        g_g1n[t] = p1 / den; g_g2n[t] = p2 / den;
        wpart[warp][0] = pa;
#pragma unroll
        for (int e = 0; e < E; e++) wpart[warp][1 + e] = p166[e];
        wpart[warp][9] = lse * lse;
#pragma unroll
        for (int e = 0; e < E; e++) wpart[warp][10 + e] = p[e];
#pragma unroll
        for (int e = 0; e < E; e++) wpart[warp][18 + e] = (e == e1) ? 1.f : 0.f;
    }
    __syncthreads();
    if (tid < 26) {
        float sum = 0.f;
        for (int w = 0; w < 8; w++) sum += wpart[w][tid];
        g_part[blockIdx.x * 26 + tid] = sum;
    }
}

// deterministic fixed-order reduction of per-block partials
__global__ void reduce_kernel() {
    int j = threadIdx.x;
    if (j < 26) {
        float s = 0.f;
        for (int b = 0; b < T / 8; b++) s += g_part[b * 26 + j];
        g_red[j] = s;
    }
}

// ---------------- per-expert prefix-sum positions, masks, index tables -------
__global__ void scan_kernel(const float* __restrict__ rnd) {
    __shared__ int s[E][1024];
    int tid = threadIdx.x;
    for (int i = tid; i < 2 * E * CAP; i += 1024) ((int*)g_idx)[i] = -1;

    int t0 = tid * 8;

    // ---- slot 1 ----
    int ev[8];
#pragma unroll
    for (int j = 0; j < 8; j++) ev[j] = g_e1[t0 + j];
    int c[E];
#pragma unroll
    for (int e = 0; e < E; e++) c[e] = 0;
#pragma unroll
    for (int j = 0; j < 8; j++) c[ev[j]]++;
#pragma unroll
    for (int e = 0; e < E; e++) s[e][tid] = c[e];
    __syncthreads();
    for (int off = 1; off < 1024; off <<= 1) {
        int r[E];
#pragma unroll
        for (int e = 0; e < E; e++) r[e] = (tid >= off) ? s[e][tid - off] : 0;
        __syncthreads();
#pragma unroll
        for (int e = 0; e < E; e++) s[e][tid] += r[e];
        __syncthreads();
    }
    int excl[E], tot[E];
#pragma unroll
    for (int e = 0; e < E; e++) { excl[e] = s[e][tid] - c[e]; tot[e] = s[e][1023]; }

    float impL[E];
#pragma unroll
    for (int e = 0; e < E; e++) impL[e] = 0.f;

#pragma unroll
    for (int j = 0; j < 8; j++) {
        int t = t0 + j, e = ev[j];
        int p = excl[e]++;
        bool mk = p < CAP;
        float w = mk ? g_g1n[t] : 0.f;
        g_ws[0][t] = w;
        if (mk) { g_idx[0][e * CAP + p] = t; g_row[0][t] = e * CAP + p; }
        else    { g_row[0][t] = -1; }
        impL[e] += w;
    }
    if (tid == 0)
        for (int e = 0; e < E; e++) g_cnt[0][e] = tot[e] < CAP ? tot[e] : CAP;
    __syncthreads();

    // ---- slot 2 ----
#pragma unroll
    for (int j = 0; j < 8; j++) ev[j] = g_e2[t0 + j];
#pragma unroll
    for (int e = 0; e < E; e++) c[e] = 0;
#pragma unroll
    for (int j = 0; j < 8; j++) c[ev[j]]++;
#pragma unroll
    for (int e = 0; e < E; e++) s[e][tid] = c[e];
    __syncthreads();
    for (int off = 1; off < 1024; off <<= 1) {
        int r[E];
#pragma unroll
        for (int e = 0; e < E; e++) r[e] = (tid >= off) ? s[e][tid - off] : 0;
        __syncthreads();
#pragma unroll
        for (int e = 0; e < E; e++) s[e][tid] += r[e];
        __syncthreads();
    }
#pragma unroll
    for (int e = 0; e < E; e++) { excl[e] = s[e][tid] - c[e]; tot[e] = s[e][1023]; }

#pragma unroll
    for (int j = 0; j < 8; j++) {
        int t = t0 + j, e = ev[j];
        int p = excl[e]++;
        float g2n = g_g2n[t];
        bool mk = (p < CAP) && (rnd[t] < 2.f * g2n);
        float w = mk ? g2n : 0.f;
        g_ws[1][t] = w;
        if (mk) { g_idx[1][e * CAP + p] = t; g_row[1][t] = e * CAP + p; }
        else    { g_row[1][t] = -1; }
        impL[e] += w;
    }
    if (tid == 0)
        for (int e = 0; e < E; e++) g_cnt[1][e] = tot[e] < CAP ? tot[e] : CAP;
    __syncthreads();

    // ---- deterministic imp reduction (reuse smem as float) ----
    float* f = (float*)s;
#pragma unroll
    for (int e = 0; e < E; e++) f[e * 1024 + tid] = impL[e];
    __syncthreads();
    for (int off = 512; off; off >>= 1) {
        if (tid < off)
#pragma unroll
            for (int e = 0; e < E; e++) f[e * 1024 + tid] += f[e * 1024 + tid + off];
        __syncthreads();
    }
    if (tid < E) g_imp[tid] = f[tid * 1024];
}

// ---------------- aux scalar -------------------------------------------------
__global__ void aux_kernel(float* __restrict__ out) {
    if (threadIdx.x == 0) {
        const float Tf = (float)T;
        float penalty_a = g_red[0] / (Tf * (float)E);
        float pb_acc = 0.f;
        for (int e = 0; e < E; e++) { float pm = g_red[1 + e] / Tf; pb_acc += pm * (1.f - pm); }
        float penalty_b = 1.f / (float)E - pb_acc / (float)E;
        float penalty = W_PEN * (penalty_a + penalty_b);
        float z = LAMBDA_Z * g_red[9] / Tf;
        float load = 0.f;
        for (int e = 0; e < E; e++) load += (g_red[18 + e] / Tf) * (g_red[10 + e] / Tf);
        load *= W_LOAD * (float)E;
        float mean = 0.f;
        for (int e = 0; e < E; e++) mean += g_imp[e];
        mean /= (float)E;
        float var = 0.f;
        for (int e = 0; e < E; e++) { float d = g_imp[e] - mean; var += d * d; }
        var /= (float)E;
        float imp_loss = W_IMP * var / (mean * mean);
        out[(size_t)T * D] = penalty + z + load + imp_loss;
    }
}

// ---------------- FFN GEMM 1: H = gelu(gather(X) @ w1 + b1) ------------------
__global__ __launch_bounds__(256) void ffn1_kernel(const float* __restrict__ x,
                                                   const float* __restrict__ w1,
                                                   const float* __restrict__ b1) {
    int g = blockIdx.z, slot = g >> 3, e = g & 7;
    int cnt = g_cnt[slot][e];
    int m0 = blockIdx.y * 128;
    if (m0 >= cnt) return;
    int n0 = blockIdx.x * 128;

    __shared__ float As[2][8][128];
    __shared__ float Bs[2][8][128];
    __shared__ int rows[128];
    int tid = threadIdx.x;
    if (tid < 128) rows[tid] = g_idx[slot][e * CAP + m0 + tid];
    __syncthreads();

    int am = tid & 127, ak = (tid >> 7) << 2;
    int bk = tid >> 5,  bn = (tid & 31) << 2;
    const float* Ap = (rows[am] >= 0) ? (x + (size_t)rows[am] * D + ak) : nullptr;
    const float* Bp = w1 + (size_t)e * D * FF + (size_t)bk * FF + n0 + bn;

    float4 af = Ap ? *(const float4*)Ap : make_float4(0.f, 0.f, 0.f, 0.f);
    float4 bf = *(const float4*)Bp;
    As[0][ak + 0][am] = af.x; As[0][ak + 1][am] = af.y;
    As[0][ak + 2][am] = af.z; As[0][ak + 3][am] = af.w;
    *(float4*)&Bs[0][bk][bn] = bf;
    __syncthreads();

    int tx = tid & 15, ty = tid >> 4;
    ull acc[8][4];
#pragma unroll
    for (int i = 0; i < 8; i++)
#pragma unroll
        for (int j = 0; j < 4; j++) acc[i][j] = 0ull;

    int buf = 0;
    for (int kb = 0; kb < D; kb += 8) {
        float4 af2, bf2;
        bool more = (kb + 8) < D;
        if (more) {
            af2 = Ap ? *(const float4*)(Ap + kb + 8) : make_float4(0.f, 0.f, 0.f, 0.f);
            bf2 = *(const float4*)(Bp + (size_t)(kb + 8) * FF);
        }
#pragma unroll
        for (int kk = 0; kk < 8; kk++) {
            const ull* b2 = (const ull*)&Bs[buf][kk][tx * 8];
            ull bq0 = b2[0], bq1 = b2[1], bq2 = b2[2], bq3 = b2[3];
#pragma unroll
            for (int i = 0; i < 8; i++) {
                ull ap = pack2(As[buf][kk][ty * 8 + i]);
                fma2(acc[i][0], ap, bq0);
                fma2(acc[i][1], ap, bq1);
                fma2(acc[i][2], ap, bq2);
                fma2(acc[i][3], ap, bq3);
            }
        }
        if (more) {
            int nb = buf ^ 1;
            As[nb][ak + 0][am] = af2.x; As[nb][ak + 1][am] = af2.y;
            As[nb][ak + 2][am] = af2.z; As[nb][ak + 3][am] = af2.w;
            *(float4*)&Bs[nb][bk][bn] = bf2;
            __syncthreads();
            buf = nb;
        }
    }

    const float* be = b1 + e * FF + n0 + tx * 8;
#pragma unroll
    for (int i = 0; i < 8; i++) {
        int m = m0 + ty * 8 + i;
        float2 u0 = unpack2(acc[i][0]), u1 = unpack2(acc[i][1]);
        float2 u2 = unpack2(acc[i][2]), u3 = unpack2(acc[i][3]);
        float o[8] = { u0.x, u0.y, u1.x, u1.y, u2.x, u2.y, u3.x, u3.y };
#pragma unroll
        for (int n = 0; n < 8; n++) o[n] = gelu_tanh(o[n] + be[n]);
        size_t base = ((size_t)g * CAP + m) * FF + n0 + tx * 8;
        *(float4*)&g_H[base]     = make_float4(o[0], o[1], o[2], o[3]);
        *(float4*)&g_H[base + 4] = make_float4(o[4], o[5], o[6], o[7]);
    }
}

// ---------------- FFN GEMM 2: Y = H @ w2 + b2 --------------------------------
__global__ __launch_bounds__(256) void ffn2_kernel(const float* __restrict__ w2,
                                                   const float* __restrict__ b2) {
    int g = blockIdx.z, slot = g >> 3, e = g & 7;
    int cnt = g_cnt[slot][e];
    int m0 = blockIdx.y * 128;
    if (m0 >= cnt) return;
    int n0 = blockIdx.x * 128;

    __shared__ float As[2][8][128];
    __shared__ float Bs[2][8][128];
    int tid = threadIdx.x;

    int am = tid & 127, ak = (tid >> 7) << 2;
    int bk = tid >> 5,  bn = (tid & 31) << 2;
    const float* Ap = g_H + ((size_t)g * CAP + m0 + am) * FF + ak;
    const float* Bp = w2 + (size_t)e * FF * D + (size_t)bk * D + n0 + bn;

    float4 af = *(const float4*)Ap;
    float4 bf = *(const float4*)Bp;
    As[0][ak + 0][am] = af.x; As[0][ak + 1][am] = af.y;
    As[0][ak + 2][am] = af.z; As[0][ak + 3][am] = af.w;
    *(float4*)&Bs[0][bk][bn] = bf;
    __syncthreads();

    int tx = tid & 15, ty = tid >> 4;
    ull acc[8][4];
#pragma unroll
    for (int i = 0; i < 8; i++)
#pragma unroll
        for (int j = 0; j < 4; j++) acc[i][j] = 0ull;

    int buf = 0;
    for (int kb = 0; kb < FF; kb += 8) {
        float4 af2, bf2;
        bool more = (kb + 8) < FF;
        if (more) {
            af2 = *(const float4*)(Ap + kb + 8);
            bf2 = *(const float4*)(Bp + (size_t)(kb + 8) * D);
        }
#pragma unroll
        for (int kk = 0; kk < 8; kk++) {
            const ull* b2v = (const ull*)&Bs[buf][kk][tx * 8];
            ull bq0 = b2v[0], bq1 = b2v[1], bq2 = b2v[2], bq3 = b2v[3];
#pragma unroll
            for (int i = 0; i < 8; i++) {
                ull ap = pack2(As[buf][kk][ty * 8 + i]);
                fma2(acc[i][0], ap, bq0);
                fma2(acc[i][1], ap, bq1);
                fma2(acc[i][2], ap, bq2);
                fma2(acc[i][3], ap, bq3);
            }
        }
        if (more) {
            int nb = buf ^ 1;
            As[nb][ak + 0][am] = af2.x; As[nb][ak + 1][am] = af2.y;
            As[nb][ak + 2][am] = af2.z; As[nb][ak + 3][am] = af2.w;
            *(float4*)&Bs[nb][bk][bn] = bf2;
            __syncthreads();
            buf = nb;
        }
    }

    const float* be = b2 + e * D + n0 + tx * 8;
#pragma unroll
    for (int i = 0; i < 8; i++) {
        int m = m0 + ty * 8 + i;
        float2 u0 = unpack2(acc[i][0]), u1 = unpack2(acc[i][1]);
        float2 u2 = unpack2(acc[i][2]), u3 = unpack2(acc[i][3]);
        float o[8] = { u0.x, u0.y, u1.x, u1.y, u2.x, u2.y, u3.x, u3.y };
#pragma unroll
        for (int n = 0; n < 8; n++) o[n] += be[n];
        size_t base = ((size_t)g * CAP + m) * D + n0 + tx * 8;
        *(float4*)&g_Y[base]     = make_float4(o[0], o[1], o[2], o[3]);
        *(float4*)&g_Y[base + 4] = make_float4(o[4], o[5], o[6], o[7]);
    }
}

// ---------------- combine: y[t] = w1*Y1[row1] + w2*Y2[row2] ------------------
__global__ void combine_kernel(float* __restrict__ out) {
    int t = blockIdx.x;
    int d = threadIdx.x * 4;
    int r1 = g_row[0][t], r2 = g_row[1][t];
    float w1 = g_ws[0][t], w2 = g_ws[1][t];
    float4 v = make_float4(0.f, 0.f, 0.f, 0.f);
    if (r1 >= 0) {
        float4 a = *(const float4*)&g_Y[(size_t)r1 * D + d];
        v.x = w1 * a.x; v.y = w1 * a.y; v.z = w1 * a.z; v.w = w1 * a.w;
    }
    if (r2 >= 0) {
        float4 a = *(const float4*)&g_Y[((size_t)E * CAP + r2) * D + d];
        v.x += w2 * a.x; v.y += w2 * a.y; v.z += w2 * a.z; v.w += w2 * a.w;
    }
    *(float4*)&out[(size_t)t * D + d] = v;
}

// ---------------- launcher ---------------------------------------------------
extern "C" void kernel_launch(void* const* d_in, const int* in_sizes, int n_in,
                              void* d_out, int out_size) {
    const float* x   = (const float*)d_in[0];
    const float* gw  = (const float*)d_in[1];
    const float* w1  = (const float*)d_in[2];
    const float* b1  = (const float*)d_in[3];
    const float* w2  = (const float*)d_in[4];
    const float* b2  = (const float*)d_in[5];
    const float* rnd = (const float*)d_in[6];
    float* out = (float*)d_out;

    gate_kernel<<<T / 8, 256>>>(x, gw);
    reduce_kernel<<<1, 32>>>();
    scan_kernel<<<1, 1024>>>(rnd);
    aux_kernel<<<1, 32>>>(out);
    ffn1_kernel<<<dim3(FF / 128, CAP / 128, 2 * E), 256>>>(x, w1, b1);
    ffn2_kernel<<<dim3(D / 128, CAP / 128, 2 * E), 256>>>(w2, b2);
    combine_kernel<<<T, 256>>>(out);
}

// round 5
// speedup vs baseline: 6.7757x; 6.7739x over previous
#include <cuda_runtime.h>
#include <cuda_fp16.h>
#include <cstdint>

#define D    1024
#define E    8
#define FF   4096
#define CAP  2048
#define T    8192
#define W_IMP    0.01f
#define W_LOAD   0.01f
#define LAMBDA_Z 0.001f
#define W_PEN    0.01f

// ---------------- device scratch ---------------------------------------------
__device__ int   g_e1[T], g_e2[T];
__device__ float g_g1n[T], g_g2n[T];
__device__ float g_ws[2][T];
__device__ int   g_row[2][T];
__device__ int   g_idx[2][E * CAP];
__device__ int   g_cnt[2][E];
__device__ float g_part[(T / 8) * 26];
__device__ float g_red[26];
__device__ float g_imp[E];
__device__ __half g_Hh[(size_t)2 * E * CAP * FF];   // 256 MB fp16 hidden
__device__ float  g_Y[(size_t)2 * E * CAP * D];     // 128 MB fp32 output
__device__ __half g_Xh[(size_t)T * D];
__device__ __half g_W1h[(size_t)E * D * FF];
__device__ __half g_W2h[(size_t)E * FF * D];

// ---------------- helpers ----------------------------------------------------
__device__ __forceinline__ uint32_t smem_u32(const void* p) {
    uint32_t a;
    asm("{ .reg .u64 t; cvta.to.shared.u64 t, %1; cvt.u32.u64 %0, t; }" : "=r"(a) : "l"(p));
    return a;
}
__device__ __forceinline__ float gelu_tanh(float v) {
    const float c = 0.7978845608028654f;
    float u = c * (v + 0.044715f * v * v * v);
    return 0.5f * v * (1.0f + tanhf(u));
}
__device__ __forceinline__ void cp16(uint32_t s, const void* g, uint32_t ssz) {
    asm volatile("cp.async.cg.shared.global [%0], [%1], 16, %2;"
                 :: "r"(s), "l"(g), "r"(ssz));
}
__device__ __forceinline__ void ldsm4(uint32_t* r, uint32_t addr) {
    asm volatile("ldmatrix.sync.aligned.m8n8.x4.shared.b16 {%0,%1,%2,%3}, [%4];"
                 : "=r"(r[0]), "=r"(r[1]), "=r"(r[2]), "=r"(r[3]) : "r"(addr));
}
__device__ __forceinline__ void ldsm4t(uint32_t* r, uint32_t addr) {
    asm volatile("ldmatrix.sync.aligned.m8n8.x4.trans.shared.b16 {%0,%1,%2,%3}, [%4];"
                 : "=r"(r[0]), "=r"(r[1]), "=r"(r[2]), "=r"(r[3]) : "r"(addr));
}
__device__ __forceinline__ void mma16816(float* c, const uint32_t* a, const uint32_t* b) {
    asm volatile("mma.sync.aligned.m16n8k16.row.col.f32.f16.f16.f32 "
                 "{%0,%1,%2,%3}, {%4,%5,%6,%7}, {%8,%9}, {%0,%1,%2,%3};"
                 : "+f"(c[0]), "+f"(c[1]), "+f"(c[2]), "+f"(c[3])
                 : "r"(a[0]), "r"(a[1]), "r"(a[2]), "r"(a[3]), "r"(b[0]), "r"(b[1]));
}

// ---------------- fp32 -> fp16 convert ---------------------------------------
__global__ void f2h_kernel(const float* __restrict__ src, __half* __restrict__ dst) {
    int i = blockIdx.x * blockDim.x + threadIdx.x;
    float4 v = ((const float4*)src)[i];
    __half2 a = __floats2half2_rn(v.x, v.y), b = __floats2half2_rn(v.z, v.w);
    ((__half2*)dst)[i * 2] = a;
    ((__half2*)dst)[i * 2 + 1] = b;
}

// ---------------- gating -----------------------------------------------------
__global__ void gate_kernel(const float* __restrict__ x, const float* __restrict__ gw) {
    __shared__ float sgw[E * D];
    __shared__ float wpart[8][26];
    int tid = threadIdx.x;
    for (int i = tid; i < E * D; i += 256) sgw[i] = gw[i];
    __syncthreads();
    int warp = tid >> 5, lane = tid & 31;
    int t = blockIdx.x * 8 + warp;
    float acc[E];
#pragma unroll
    for (int e = 0; e < E; e++) acc[e] = 0.f;
    const float* xr = x + (size_t)t * D;
#pragma unroll 4
    for (int j = 0; j < D / 32; j++) {
        float xv = xr[j * 32 + lane];
#pragma unroll
        for (int e = 0; e < E; e++) acc[e] += xv * sgw[e * D + j * 32 + lane];
    }
#pragma unroll
    for (int e = 0; e < E; e++)
#pragma unroll
        for (int off = 16; off; off >>= 1)
            acc[e] += __shfl_xor_sync(0xffffffffu, acc[e], off);
    float m = acc[0];
#pragma unroll
    for (int e = 1; e < E; e++) m = fmaxf(m, acc[e]);
    float p166[E]; float s166 = 0.f;
#pragma unroll
    for (int e = 0; e < E; e++) { p166[e] = expf((acc[e] - m) / 1.66f); s166 += p166[e]; }
    float pa = 0.f;
#pragma unroll
    for (int e = 0; e < E; e++) { p166[e] /= s166; pa += p166[e] * (1.f - p166[e]); }
    float p[E]; float s = 0.f;
#pragma unroll
    for (int e = 0; e < E; e++) { p[e] = expf(acc[e] - m); s += p[e]; }
    float lse = m + logf(s);
#pragma unroll
    for (int e = 0; e < E; e++) p[e] /= s;
    int e1 = 0; float p1 = p[0];
#pragma unroll
    for (int e = 1; e < E; e++) if (p[e] > p1) { p1 = p[e]; e1 = e; }
    int e2 = -1; float p2 = -1.f;
#pragma unroll
    for (int e = 0; e < E; e++) if (e != e1 && p[e] > p2) { p2 = p[e]; e2 = e; }
    float den = p1 + p2;
    if (lane == 0) {
        g_e1[t] = e1; g_e2[t] = e2;
        g_g1n[t] = p1 / den; g_g2n[t] = p2 / den;
        wpart[warp][0] = pa;
#pragma unroll
        for (int e = 0; e < E; e++) wpart[warp][1 + e] = p166[e];
        wpart[warp][9] = lse * lse;
#pragma unroll
        for (int e = 0; e < E; e++) wpart[warp][10 + e] = p[e];
#pragma unroll
        for (int e = 0; e < E; e++) wpart[warp][18 + e] = (e == e1) ? 1.f : 0.f;
    }
    __syncthreads();
    if (tid < 26) {
        float sum = 0.f;
        for (int w = 0; w < 8; w++) sum += wpart[w][tid];
        g_part[blockIdx.x * 26 + tid] = sum;
    }
}

__global__ void reduce_kernel() {
    int j = threadIdx.x;
    if (j < 26) {
        float s = 0.f;
        for (int b = 0; b < T / 8; b++) s += g_part[b * 26 + j];
        g_red[j] = s;
    }
}

// ---------------- scan -------------------------------------------------------
__global__ void scan_kernel(const float* __restrict__ rnd) {
    __shared__ int s[E][1024];
    int tid = threadIdx.x;
    for (int i = tid; i < 2 * E * CAP; i += 1024) ((int*)g_idx)[i] = -1;
    int t0 = tid * 8;
    int ev[8];
#pragma unroll
    for (int j = 0; j < 8; j++) ev[j] = g_e1[t0 + j];
    int c[E];
#pragma unroll
    for (int e = 0; e < E; e++) c[e] = 0;
#pragma unroll
    for (int j = 0; j < 8; j++) c[ev[j]]++;
#pragma unroll
    for (int e = 0; e < E; e++) s[e][tid] = c[e];
    __syncthreads();
    for (int off = 1; off < 1024; off <<= 1) {
        int r[E];
#pragma unroll
        for (int e = 0; e < E; e++) r[e] = (tid >= off) ? s[e][tid - off] : 0;
        __syncthreads();
#pragma unroll
        for (int e = 0; e < E; e++) s[e][tid] += r[e];
        __syncthreads();
    }
    int excl[E], tot[E];
#pragma unroll
    for (int e = 0; e < E; e++) { excl[e] = s[e][tid] - c[e]; tot[e] = s[e][1023]; }
    float impL[E];
#pragma unroll
    for (int e = 0; e < E; e++) impL[e] = 0.f;
#pragma unroll
    for (int j = 0; j < 8; j++) {
        int t = t0 + j, e = ev[j];
        int p = excl[e]++;
        bool mk = p < CAP;
        float w = mk ? g_g1n[t] : 0.f;
        g_ws[0][t] = w;
        if (mk) { g_idx[0][e * CAP + p] = t; g_row[0][t] = e * CAP + p; }
        else    { g_row[0][t] = -1; }
        impL[e] += w;
    }
    if (tid == 0)
        for (int e = 0; e < E; e++) g_cnt[0][e] = tot[e] < CAP ? tot[e] : CAP;
    __syncthreads();
#pragma unroll
    for (int j = 0; j < 8; j++) ev[j] = g_e2[t0 + j];
#pragma unroll
    for (int e = 0; e < E; e++) c[e] = 0;
#pragma unroll
    for (int j = 0; j < 8; j++) c[ev[j]]++;
#pragma unroll
    for (int e = 0; e < E; e++) s[e][tid] = c[e];
    __syncthreads();
    for (int off = 1; off < 1024; off <<= 1) {
        int r[E];
#pragma unroll
        for (int e = 0; e < E; e++) r[e] = (tid >= off) ? s[e][tid - off] : 0;
        __syncthreads();
#pragma unroll
        for (int e = 0; e < E; e++) s[e][tid] += r[e];
        __syncthreads();
    }
#pragma unroll
    for (int e = 0; e < E; e++) { excl[e] = s[e][tid] - c[e]; tot[e] = s[e][1023]; }
#pragma unroll
    for (int j = 0; j < 8; j++) {
        int t = t0 + j, e = ev[j];
        int p = excl[e]++;
        float g2n = g_g2n[t];
        bool mk = (p < CAP) && (rnd[t] < 2.f * g2n);
        float w = mk ? g2n : 0.f;
        g_ws[1][t] = w;
        if (mk) { g_idx[1][e * CAP + p] = t; g_row[1][t] = e * CAP + p; }
        else    { g_row[1][t] = -1; }
        impL[e] += w;
    }
    if (tid == 0)
        for (int e = 0; e < E; e++) g_cnt[1][e] = tot[e] < CAP ? tot[e] : CAP;
    __syncthreads();
    float* f = (float*)s;
#pragma unroll
    for (int e = 0; e < E; e++) f[e * 1024 + tid] = impL[e];
    __syncthreads();
    for (int off = 512; off; off >>= 1) {
        if (tid < off)
#pragma unroll
            for (int e = 0; e < E; e++) f[e * 1024 + tid] += f[e * 1024 + tid + off];
        __syncthreads();
    }
    if (tid < E) g_imp[tid] = f[tid * 1024];
}

// ---------------- aux --------------------------------------------------------
__global__ void aux_kernel(float* __restrict__ out) {
    if (threadIdx.x == 0) {
        const float Tf = (float)T;
        float penalty_a = g_red[0] / (Tf * (float)E);
        float pb_acc = 0.f;
        for (int e = 0; e < E; e++) { float pm = g_red[1 + e] / Tf; pb_acc += pm * (1.f - pm); }
        float penalty_b = 1.f / (float)E - pb_acc / (float)E;
        float penalty = W_PEN * (penalty_a + penalty_b);
        float z = LAMBDA_Z * g_red[9] / Tf;
        float load = 0.f;
        for (int e = 0; e < E; e++) load += (g_red[18 + e] / Tf) * (g_red[10 + e] / Tf);
        load *= W_LOAD * (float)E;
        float mean = 0.f;
        for (int e = 0; e < E; e++) mean += g_imp[e];
        mean /= (float)E;
        float var = 0.f;
        for (int e = 0; e < E; e++) { float d = g_imp[e] - mean; var += d * d; }
        var /= (float)E;
        float imp_loss = W_IMP * var / (mean * mean);
        out[(size_t)T * D] = penalty + z + load + imp_loss;
    }
}

// ---------------- fp16 mma.sync grouped GEMM ---------------------------------
// CTA tile 128x128, warps 4(M)x2(N), warp tile 32x64, K-stage 32, 3-stage ring.
#define KBLK    32
#define STAGES  3
#define A_STRIDE 80                   // bytes per A row (32 halves + 16B pad)
#define A_BYTES (128 * A_STRIDE)      // 10240
#define B_BYTES (KBLK * 256)          // 8192
#define STG_BYTES (A_BYTES + B_BYTES) // 18432
#define SMEM_BYTES (STAGES * STG_BYTES + 512)

template <bool IS_FFN1>
__global__ __launch_bounds__(256, 2) void moe_mma(
    const __half* __restrict__ Ag, const __half* __restrict__ Bw,
    const float* __restrict__ biasw, void* __restrict__ Outv,
    int K, int ldA, int Ntot)
{
    extern __shared__ char smem[];
    int g = blockIdx.z;
    int cnt = (&g_cnt[0][0])[g];
    int m0 = blockIdx.y * 128;
    if (m0 >= cnt) return;
    int n0 = blockIdx.x * 128;
    int e = g & 7;
    const __half* Bh = Bw + (size_t)e * (size_t)K * Ntot;
    const float* bias = biasw + e * Ntot + n0;

    int tid = threadIdx.x, wid = tid >> 5, lane = tid & 31;
    int* rows = (int*)(smem + STAGES * STG_BYTES);
    if (tid < 128)
        rows[tid] = IS_FFN1 ? (&g_idx[0][0])[g * CAP + m0 + tid] : (g * CAP + m0 + tid);
    __syncthreads();
    uint32_t sbase = smem_u32(smem);
    int NKB = K / KBLK;

    // ---- stage loader: 1024 x 16B chunks (B:512, A:512), 4 per thread ----
    auto load_stage = [&](int kb, int st) {
        uint32_t sa = sbase + st * STG_BYTES;
        uint32_t sB = sa + A_BYTES;
        int k0 = kb * KBLK;
#pragma unroll
        for (int i = 0; i < 4; i++) {
            int c = tid + i * 256;
            if (c < 512) {                       // B: 32 k-rows x 128 halves
                int k = c >> 4, nch = c & 15;
                const void* src = Bh + (size_t)(k0 + k) * Ntot + n0 + nch * 8;
                uint32_t dst = sB + k * 256 + (((uint32_t)(nch ^ (k & 7))) << 4);
                cp16(dst, src, 16);
            } else {                             // A: 128 rows x 32 halves
                int c2 = c - 512, r = c2 >> 2, ch = c2 & 3;
                int tok = rows[r];
                uint32_t ssz = 16;
                if (IS_FFN1 && tok < 0) { tok = 0; ssz = 0; }
                const void* src = Ag + (size_t)tok * ldA + k0 + ch * 8;
                uint32_t dst = sa + r * A_STRIDE + (ch << 4);
                cp16(dst, src, ssz);
            }
        }
        asm volatile("cp.async.commit_group;" ::: "memory");
    };

    int wm = (wid & 3) * 32, wn = (wid >> 2) * 64;
    float acc[2][8][4];
#pragma unroll
    for (int mi = 0; mi < 2; mi++)
#pragma unroll
        for (int ni = 0; ni < 8; ni++)
#pragma unroll
            for (int j = 0; j < 4; j++) acc[mi][ni][j] = 0.f;

    load_stage(0, 0);
    load_stage(1, 1);

    int q = lane >> 3, r8 = lane & 7;
    for (int kb = 0; kb < NKB; kb++) {
        int st = kb % 3;
        if (kb + 1 < NKB)
            asm volatile("cp.async.wait_group 1;" ::: "memory");
        else
            asm volatile("cp.async.wait_group 0;" ::: "memory");
        __syncthreads();
        uint32_t sa = sbase + st * STG_BYTES;
        uint32_t sB = sa + A_BYTES;
#pragma unroll
        for (int ks = 0; ks < 2; ks++) {
            uint32_t af[2][4], bf[8][2];
#pragma unroll
            for (int mi = 0; mi < 2; mi++) {
                int row = wm + mi * 16 + r8 + (q & 1) * 8;
                int ch = ks * 2 + (q >> 1);
                ldsm4(af[mi], sa + row * A_STRIDE + ch * 16);
            }
#pragma unroll
            for (int i = 0; i < 4; i++) {
                int k = ks * 16 + (q & 1) * 8 + r8;
                int nch = (wn >> 3) + i * 2 + (q >> 1);
                uint32_t rr[4];
                ldsm4t(rr, sB + k * 256 + (((uint32_t)(nch ^ (k & 7))) << 4));
                bf[i * 2][0] = rr[0]; bf[i * 2][1] = rr[1];
                bf[i * 2 + 1][0] = rr[2]; bf[i * 2 + 1][1] = rr[3];
            }
#pragma unroll
            for (int mi = 0; mi < 2; mi++)
#pragma unroll
                for (int ni = 0; ni < 8; ni++)
                    mma16816(acc[mi][ni], af[mi], bf[ni]);
        }
        if (kb + 2 < NKB) load_stage(kb + 2, (kb + 2) % 3);
    }

    // ---- epilogue: bias (+gelu) -> store ----
#pragma unroll
    for (int mi = 0; mi < 2; mi++) {
#pragma unroll
        for (int ni = 0; ni < 8; ni++) {
            int row = m0 + wm + mi * 16 + (lane >> 2);
            int col = wn + ni * 8 + (lane & 3) * 2;
            float b0 = bias[col], b1 = bias[col + 1];
            float v0 = acc[mi][ni][0] + b0, v1 = acc[mi][ni][1] + b1;
            float v2 = acc[mi][ni][2] + b0, v3 = acc[mi][ni][3] + b1;
            if (IS_FFN1) {
                v0 = gelu_tanh(v0); v1 = gelu_tanh(v1);
                v2 = gelu_tanh(v2); v3 = gelu_tanh(v3);
                __half* Out = (__half*)Outv;
                size_t o = ((size_t)g * CAP + row) * Ntot + n0 + col;
                *(__half2*)(Out + o) = __floats2half2_rn(v0, v1);
                *(__half2*)(Out + o + (size_t)8 * Ntot) = __floats2half2_rn(v2, v3);
            } else {
                float* Out = (float*)Outv;
                size_t o = ((size_t)g * CAP + row) * Ntot + n0 + col;
                *(float2*)(Out + o) = make_float2(v0, v1);
                *(float2*)(Out + o + (size_t)8 * Ntot) = make_float2(v2, v3);
            }
        }
    }
}

// ---------------- combine ----------------------------------------------------
__global__ void combine_kernel(float* __restrict__ out) {
    int t = blockIdx.x;
    int d = threadIdx.x * 4;
    int r1 = g_row[0][t], r2 = g_row[1][t];
    float w1 = g_ws[0][t], w2 = g_ws[1][t];
    float4 v = make_float4(0.f, 0.f, 0.f, 0.f);
    if (r1 >= 0) {
        float4 a = *(const float4*)&g_Y[(size_t)r1 * D + d];
        v.x = w1 * a.x; v.y = w1 * a.y; v.z = w1 * a.z; v.w = w1 * a.w;
    }
    if (r2 >= 0) {
        float4 a = *(const float4*)&g_Y[((size_t)E * CAP + r2) * D + d];
        v.x += w2 * a.x; v.y += w2 * a.y; v.z += w2 * a.z; v.w += w2 * a.w;
    }
    *(float4*)&out[(size_t)t * D + d] = v;
}

// ---------------- launcher ---------------------------------------------------
extern "C" void kernel_launch(void* const* d_in, const int* in_sizes, int n_in,
                              void* d_out, int out_size) {
    const float* x   = (const float*)d_in[0];
    const float* gw  = (const float*)d_in[1];
    const float* w1  = (const float*)d_in[2];
    const float* b1  = (const float*)d_in[3];
    const float* w2  = (const float*)d_in[4];
    const float* b2  = (const float*)d_in[5];
    const float* rnd = (const float*)d_in[6];
    float* out = (float*)d_out;

    cudaFuncSetAttribute(moe_mma<true>,
                         cudaFuncAttributeMaxDynamicSharedMemorySize, SMEM_BYTES);
    cudaFuncSetAttribute(moe_mma<false>,
                         cudaFuncAttributeMaxDynamicSharedMemorySize, SMEM_BYTES);

    __half *xh, *w1h, *w2h, *hh;
    cudaGetSymbolAddress((void**)&xh,  g_Xh);
    cudaGetSymbolAddress((void**)&w1h, g_W1h);
    cudaGetSymbolAddress((void**)&w2h, g_W2h);
    cudaGetSymbolAddress((void**)&hh,  g_Hh);
    float* yy;
    cudaGetSymbolAddress((void**)&yy, g_Y);

    gate_kernel<<<T / 8, 256>>>(x, gw);
    reduce_kernel<<<1, 32>>>();
    scan_kernel<<<1, 1024>>>(rnd);
    aux_kernel<<<1, 32>>>(out);

    f2h_kernel<<<(T * D / 4) / 256, 256>>>(x, xh);
    f2h_kernel<<<(E * D * FF / 4) / 256, 256>>>(w1, w1h);
    f2h_kernel<<<(E * FF * D / 4) / 256, 256>>>(w2, w2h);

    moe_mma<true><<<dim3(FF / 128, CAP / 128, 2 * E), 256, SMEM_BYTES>>>(
        xh, w1h, b1, (void*)hh, D, D, FF);
    moe_mma<false><<<dim3(D / 128, CAP / 128, 2 * E), 256, SMEM_BYTES>>>(
        hh, w2h, b2, (void*)yy, FF, FF, D);

    combine_kernel<<<T, 256>>>(out);
}